// round 16
// baseline (speedup 1.0000x reference)
#include <cuda_runtime.h>
#include <cuda_bf16.h>
#include <math.h>
#include <stdint.h>

typedef unsigned long long ull;

// Problem constants (fixed by setup_inputs)
static const int cB  = 2;
static const int cN  = 512;
static const int cCS = 384;
static const int cCZ = 128;
static const int cH  = 12;
static const int cCH = 32;
static const int cPQ = 4;
static const int cPV = 8;
static const int cHID = 1536;
static const int cBN = 1024;
static const int cCAT = 2304;
static const int cPROJ = 1728;

#define WL   0.5773502691896258f
#define WCC  0.23570226039551584f
#define C2   (0.5f*WL*WCC)
#define CATT (WL*0.17677669529663687f)

// weight-split arena offsets (u32 units)
#define OFF_WCAT 0
#define OFF_WOUT 331776
#define OFF_W12  774144
#define OFF_W3   1363968
#define W_ARENA  1658880

// ---------------- scratch (device globals) ----------------------------------
__device__ float g_wcat [cPROJ*cCS];
__device__ float g_s0   [cBN*cCS];
__device__ float g_proj [cBN*cPROJ];
__device__ float g_q    [cBN*cH*cCH];
__device__ float g_k    [cBN*cH*cCH];
__device__ float g_v    [cBN*cH*cCH];
__device__ float g_qps  [cBN*cH*cPQ*3];
__device__ float g_kp   [cBN*cH*cPQ*3];
__device__ float g_vp   [cBN*cH*cPV*3];
__device__ float g_qn   [cBN*cH];
__device__ float g_kn   [cBN*cH];
__device__ float g_P    [(size_t)cB*cH*cN*cN];
__device__ float g_att  [(size_t)cB*cH*cN*cN];
__device__ float g_rsc  [(size_t)cBN*cN];
__device__ float g_opg  [cBN*cH*cPV*3];
__device__ float g_cat  [cBN*cCAT];
__device__ float g_s1   [cBN*cCS];
__device__ float g_x    [cBN*cCS];
__device__ float g_hh   [cBN*2*cHID];
__device__ float g_x3   [cBN*cCS];
__device__ float g_part [4*cBN*cCS];
// split-bf16 packed operand buffers
__device__ unsigned g_ahi[1152*1024];
__device__ unsigned g_alo[1152*1024];
__device__ unsigned g_whi[W_ARENA];
__device__ unsigned g_wlo[W_ARENA];

// packed fp32x2 helpers (Blackwell)
__device__ __forceinline__ ull ffma2(ull a, ull b, ull c) {
    ull d;
    asm("fma.rn.f32x2 %0, %1, %2, %3;" : "=l"(d) : "l"(a), "l"(b), "l"(c));
    return d;
}
__device__ __forceinline__ ull dup2(float v) {
    ull d; unsigned u = __float_as_uint(v);
    asm("mov.b64 %0, {%1, %1};" : "=l"(d) : "r"(u));
    return d;
}
__device__ __forceinline__ float f2lo(ull p){ return __uint_as_float((unsigned)p); }
__device__ __forceinline__ float f2hi(ull p){ return __uint_as_float((unsigned)(p>>32)); }

// cp.async helpers
__device__ __forceinline__ void cpasync8(void* smem, const void* gmem) {
    unsigned s = (unsigned)__cvta_generic_to_shared(smem);
    asm volatile("cp.async.ca.shared.global [%0], [%1], 8;" :: "r"(s), "l"(gmem));
}
__device__ __forceinline__ void cpasync16(void* smem, const void* gmem) {
    unsigned s = (unsigned)__cvta_generic_to_shared(smem);
    asm volatile("cp.async.cg.shared.global [%0], [%1], 16;" :: "r"(s), "l"(gmem));
}
#define CP_COMMIT() asm volatile("cp.async.commit_group;")
#define CP_WAIT1()  asm volatile("cp.async.wait_group 1;")
#define CP_WAIT0()  asm volatile("cp.async.wait_group 0;")

// bf16 split-pack
__device__ __forceinline__ void splitpack(float x, float y, unsigned &hi, unsigned &lo) {
    __nv_bfloat16 xh = __float2bfloat16(x), yh = __float2bfloat16(y);
    float xr = x - __bfloat162float(xh), yr = y - __bfloat162float(yh);
    __nv_bfloat16 xl = __float2bfloat16(xr), yl = __float2bfloat16(yr);
    hi = (unsigned)__bfloat16_as_ushort(xh) | ((unsigned)__bfloat16_as_ushort(yh) << 16);
    lo = (unsigned)__bfloat16_as_ushort(xl) | ((unsigned)__bfloat16_as_ushort(yl) << 16);
}

// m16n8k16 bf16 MMA
__device__ __forceinline__ void mma16816(float* d, const unsigned* a, unsigned b0, unsigned b1) {
    asm("mma.sync.aligned.m16n8k16.row.col.f32.bf16.bf16.f32 "
        "{%0,%1,%2,%3}, {%4,%5,%6,%7}, {%8,%9}, {%0,%1,%2,%3};"
        : "+f"(d[0]), "+f"(d[1]), "+f"(d[2]), "+f"(d[3])
        : "r"(a[0]), "r"(a[1]), "r"(a[2]), "r"(a[3]), "r"(b0), "r"(b1));
}

// ---------------- RMSNorm ----------------------------------------------------
__global__ __launch_bounds__(128) void rmsnorm_kernel(
    const float* __restrict__ in, const float* __restrict__ w,
    float* __restrict__ out, int C)
{
    int row = blockIdx.x;
    const float* x = in + (size_t)row * C;
    float ss = 0.f;
    for (int i = threadIdx.x; i < C; i += 128) { float v = x[i]; ss += v*v; }
    __shared__ float red[4];
    #pragma unroll
    for (int o = 16; o; o >>= 1) ss += __shfl_xor_sync(0xffffffffu, ss, o);
    if ((threadIdx.x & 31) == 0) red[threadIdx.x >> 5] = ss;
    __syncthreads();
    float tot = red[0] + red[1] + red[2] + red[3];
    float r = rsqrtf(tot / (float)C + 1e-6f);
    float* o2 = out + (size_t)row * C;
    for (int i = threadIdx.x; i < C; i += 128) o2[i] = x[i] * r * w[i];
}

// ---------------- fused: sum 4 split-K partials + resid -> Cs; rmsnorm -> Cx -
__global__ __launch_bounds__(128) void combine4_rms_kernel(
    const float* __restrict__ resid, const float* __restrict__ w,
    float* __restrict__ Cs, float* __restrict__ Cx)
{
    int row = blockIdx.x;
    int t = threadIdx.x;
    float vals[3];
    float ss = 0.f;
    #pragma unroll
    for (int i = 0; i < 3; i++) {
        int c = t + i*128;
        size_t idx = (size_t)row*384 + c;
        float v = g_part[idx] + g_part[idx + 393216] + g_part[idx + 786432]
                + g_part[idx + 1179648] + resid[idx];
        vals[i] = v; ss += v*v;
    }
    __shared__ float red[4];
    #pragma unroll
    for (int o = 16; o; o >>= 1) ss += __shfl_xor_sync(0xffffffffu, ss, o);
    if ((t & 31) == 0) red[t >> 5] = ss;
    __syncthreads();
    float tot = red[0] + red[1] + red[2] + red[3];
    float r = rsqrtf(tot * (1.f/384.f) + 1e-6f);
    #pragma unroll
    for (int i = 0; i < 3; i++) {
        int c = t + i*128;
        size_t idx = (size_t)row*384 + c;
        Cs[idx] = vals[i];
        Cx[idx] = vals[i] * r * w[c];
    }
}

// ---------------- concat projection weights ---------------------------------
__global__ __launch_bounds__(256) void wcat_kernel(
    const float* __restrict__ wq, const float* __restrict__ wqp,
    const float* __restrict__ wkp, const float* __restrict__ wvp)
{
    int i = blockIdx.x * 256 + threadIdx.x;
    if (i >= cPROJ * 96) return;
    int row = i / 96, c4 = i - row * 96;
    float4 v;
    if      (row < 1152) v = ((const float4*)wq )[(size_t)row*96 + c4];
    else if (row < 1296) v = ((const float4*)wqp)[(size_t)(row-1152)*96 + c4];
    else if (row < 1440) v = ((const float4*)wkp)[(size_t)(row-1296)*96 + c4];
    else                 v = ((const float4*)wvp)[(size_t)(row-1440)*96 + c4];
    ((float4*)g_wcat)[i] = v;
}

// ---------------- tiled transpose + bf16 split ------------------------------
__global__ __launch_bounds__(256) void split_t_kernel(
    const float* __restrict__ A, unsigned* __restrict__ Hi, unsigned* __restrict__ Lo,
    int K, int outStride)
{
    __shared__ float tile[64][65];
    int r0 = blockIdx.x * 64;
    int k0 = blockIdx.y * 64;
    int tid = threadIdx.x;
    #pragma unroll
    for (int i = 0; i < 4; i++) {
        int l = tid + i*256;
        int r = l >> 4, c4 = (l & 15)*4;
        float4 v = *(const float4*)(A + (size_t)(r0 + r)*K + k0 + c4);
        tile[r][c4+0]=v.x; tile[r][c4+1]=v.y; tile[r][c4+2]=v.z; tile[r][c4+3]=v.w;
    }
    __syncthreads();
    int kp0 = k0 >> 1;
    #pragma unroll
    for (int i = 0; i < 8; i++) {
        int l = tid + i*256;
        int kp = l >> 6, r = l & 63;
        unsigned hi, lo;
        splitpack(tile[r][kp*2], tile[r][kp*2+1], hi, lo);
        Hi[(size_t)(kp0+kp)*outStride + r0 + r] = hi;
        Lo[(size_t)(kp0+kp)*outStride + r0 + r] = lo;
    }
}

// gated variant
__global__ __launch_bounds__(256) void split_gated_t_kernel(
    unsigned* __restrict__ Hi, unsigned* __restrict__ Lo)
{
    __shared__ float tile[64][65];
    int r0 = blockIdx.x * 64;
    int k0 = blockIdx.y * 64;
    int tid = threadIdx.x;
    #pragma unroll
    for (int i = 0; i < 4; i++) {
        int l = tid + i*256;
        int r = l >> 4, c4 = (l & 15)*4;
        const float* base = g_hh + (size_t)(r0 + r)*3072 + k0 + c4;
        float4 a = *(const float4*)base;
        float4 b = *(const float4*)(base + 1536);
        tile[r][c4+0] = (a.x / (1.f + __expf(-a.x))) * b.x;
        tile[r][c4+1] = (a.y / (1.f + __expf(-a.y))) * b.y;
        tile[r][c4+2] = (a.z / (1.f + __expf(-a.z))) * b.z;
        tile[r][c4+3] = (a.w / (1.f + __expf(-a.w))) * b.w;
    }
    __syncthreads();
    int kp0 = k0 >> 1;
    #pragma unroll
    for (int i = 0; i < 8; i++) {
        int l = tid + i*256;
        int kp = l >> 6, r = l & 63;
        unsigned hi, lo;
        splitpack(tile[r][kp*2], tile[r][kp*2+1], hi, lo);
        Hi[(size_t)(kp0+kp)*1024 + r0 + r] = hi;
        Lo[(size_t)(kp0+kp)*1024 + r0 + r] = lo;
    }
}

// ---------------- bf16x3 tensor-core GEMM (cp.async double-buffered) --------
__global__ __launch_bounds__(128) void gemm_bf16_kernel(
    const unsigned* __restrict__ Ahi, const unsigned* __restrict__ Alo,
    const unsigned* __restrict__ Whi, const unsigned* __restrict__ Wlo,
    const float* __restrict__ resid, float* __restrict__ C,
    int Nn, int kpPer)
{
    __shared__ __align__(16) unsigned sAh[2][16][136], sAl[2][16][136];
    __shared__ __align__(16) unsigned sBh[2][16][72],  sBl[2][16][72];
    int bm = blockIdx.y * 128, bn = blockIdx.x * 64;
    int kp0 = blockIdx.z * kpPer;
    float* Cout = C + (size_t)blockIdx.z * 1024 * Nn;
    const float* rz = (gridDim.z == 1) ? resid : nullptr;

    int tid = threadIdx.x, wid = tid >> 5, lane = tid & 31;
    int quad = lane >> 2, tid4 = lane & 3;
    int wm = (wid & 1) * 64, wn = (wid >> 1) * 32;

    float acc[4][4][4];
    #pragma unroll
    for (int a = 0; a < 4; a++)
        #pragma unroll
        for (int b = 0; b < 4; b++)
            #pragma unroll
            for (int c = 0; c < 4; c++) acc[a][b][c] = 0.f;

    int la_r = tid >> 5, la_c4 = (tid & 31)*4;
    int lb_r = tid >> 4, lb_c4 = (tid & 15)*4;
    #define LOAD_CHUNK(kc, buf) do {                                            \
        _Pragma("unroll")                                                       \
        for (int i = 0; i < 4; i++) {                                           \
            int r = la_r + i*4;                                                 \
            size_t off = (size_t)(kp0+(kc)+r)*1024 + bm + la_c4;                \
            cpasync16(&sAh[buf][r][la_c4], Ahi + off);                          \
            cpasync16(&sAl[buf][r][la_c4], Alo + off);                          \
        }                                                                       \
        _Pragma("unroll")                                                       \
        for (int i = 0; i < 2; i++) {                                           \
            int r = lb_r + i*8;                                                 \
            size_t off = (size_t)(kp0+(kc)+r)*Nn + bn + lb_c4;                  \
            cpasync16(&sBh[buf][r][lb_c4], Whi + off);                          \
            cpasync16(&sBl[buf][r][lb_c4], Wlo + off);                          \
        }                                                                       \
        CP_COMMIT();                                                            \
    } while (0)

    LOAD_CHUNK(0, 0);

    for (int kc = 0; kc < kpPer; kc += 16) {
        int buf = (kc >> 4) & 1;
        if (kc + 16 < kpPer) {
            LOAD_CHUNK(kc + 16, buf^1);
            CP_WAIT1();
        } else {
            CP_WAIT0();
        }
        __syncthreads();
        #pragma unroll
        for (int step = 0; step < 2; step++) {
            int kb = step*8;
            unsigned ah[4][4], al[4][4];
            #pragma unroll
            for (int mt = 0; mt < 4; mt++) {
                int m = wm + mt*16 + quad;
                ah[mt][0] = sAh[buf][kb+tid4][m];
                ah[mt][1] = sAh[buf][kb+tid4][m+8];
                ah[mt][2] = sAh[buf][kb+tid4+4][m];
                ah[mt][3] = sAh[buf][kb+tid4+4][m+8];
                al[mt][0] = sAl[buf][kb+tid4][m];
                al[mt][1] = sAl[buf][kb+tid4][m+8];
                al[mt][2] = sAl[buf][kb+tid4+4][m];
                al[mt][3] = sAl[buf][kb+tid4+4][m+8];
            }
            #pragma unroll
            for (int nt = 0; nt < 4; nt++) {
                int n = wn + nt*8 + quad;
                unsigned bh0 = sBh[buf][kb+tid4][n], bh1 = sBh[buf][kb+tid4+4][n];
                unsigned bl0 = sBl[buf][kb+tid4][n], bl1 = sBl[buf][kb+tid4+4][n];
                #pragma unroll
                for (int mt = 0; mt < 4; mt++) {
                    mma16816(acc[mt][nt], ah[mt], bh0, bh1);
                    mma16816(acc[mt][nt], ah[mt], bl0, bl1);
                    mma16816(acc[mt][nt], al[mt], bh0, bh1);
                }
            }
        }
        __syncthreads();
    }
    #pragma unroll
    for (int mt = 0; mt < 4; mt++) {
        #pragma unroll
        for (int nt = 0; nt < 4; nt++) {
            int r0 = bm + wm + mt*16 + quad;
            int cc = bn + wn + nt*8 + tid4*2;
            float2 v0 = make_float2(acc[mt][nt][0], acc[mt][nt][1]);
            float2 v1 = make_float2(acc[mt][nt][2], acc[mt][nt][3]);
            if (rz) {
                const float* p0 = rz + (size_t)r0*Nn + cc;
                const float* p1 = rz + (size_t)(r0+8)*Nn + cc;
                v0.x += p0[0]; v0.y += p0[1];
                v1.x += p1[0]; v1.y += p1[1];
            }
            *(float2*)(Cout + (size_t)r0*Nn + cc)     = v0;
            *(float2*)(Cout + (size_t)(r0+8)*Nn + cc) = v1;
        }
    }
}

// ---------------- merged: split qkv + RoPE + points -------------------------
__global__ __launch_bounds__(384) void rope_points_kernel(
    const float* __restrict__ rot, const float* __restrict__ trans,
    const float* __restrict__ head_w)
{
    int row = blockIdx.x;
    int n = row & (cN - 1);
    int t = threadIdx.x;
    const float* base = g_proj + (size_t)row * cPROJ;
    __shared__ float R[9], T[3];
    __shared__ float sqp[144], skp[144];

    g_v[(size_t)row * 384 + t] = base[768 + t];
    if (t < 9) R[t] = rot[(size_t)row*9 + t];
    if (t >= 9 && t < 12) T[t-9] = trans[(size_t)row*3 + (t-9)];
    if (t < 192) {
        int h = t / 16, c = t % 16;
        float inv = powf(10000.f, -(float)c / 16.f);
        float ang = (float)n * inv;
        float sn, cs;
        sincosf(ang, &sn, &cs);
        int i1 = h*32 + c, i2 = i1 + 16;
        float q1 = base[i1],     q2 = base[i2];
        float k1 = base[384+i1], k2 = base[384+i2];
        float* qo = g_q + (size_t)row * 384;
        float* ko = g_k + (size_t)row * 384;
        qo[i1] = q1*cs - q2*sn;  qo[i2] = q1*sn + q2*cs;
        ko[i1] = k1*cs - k2*sn;  ko[i2] = k1*sn + k2*cs;
    }
    __syncthreads();
    if (t < 48) {
        const float* p = base + 1152 + t*3;
        float o0 = R[0]*p[0] + R[1]*p[1] + R[2]*p[2] + T[0];
        float o1 = R[3]*p[0] + R[4]*p[1] + R[5]*p[2] + T[1];
        float o2 = R[6]*p[0] + R[7]*p[1] + R[8]*p[2] + T[2];
        int h = t >> 2;
        float gam = log1pf(__expf(head_w[h]));
        float s = 2.f * C2 * gam;
        float* q = g_qps + (size_t)row*144 + t*3;
        q[0]=o0*s; q[1]=o1*s; q[2]=o2*s;
        sqp[t*3]=o0; sqp[t*3+1]=o1; sqp[t*3+2]=o2;
    } else if (t < 96) {
        int u = t - 48;
        const float* p = base + 1296 + u*3;
        float o0 = R[0]*p[0] + R[1]*p[1] + R[2]*p[2] + T[0];
        float o1 = R[3]*p[0] + R[4]*p[1] + R[5]*p[2] + T[1];
        float o2 = R[6]*p[0] + R[7]*p[1] + R[8]*p[2] + T[2];
        float* q = g_kp + (size_t)row*144 + u*3;
        q[0]=o0; q[1]=o1; q[2]=o2;
        skp[u*3]=o0; skp[u*3+1]=o1; skp[u*3+2]=o2;
    } else if (t < 192) {
        int u = t - 96;
        const float* p = base + 1440 + u*3;
        float o0 = R[0]*p[0] + R[1]*p[1] + R[2]*p[2] + T[0];
        float o1 = R[3]*p[0] + R[4]*p[1] + R[5]*p[2] + T[1];
        float o2 = R[6]*p[0] + R[7]*p[1] + R[8]*p[2] + T[2];
        float* q = g_vp + (size_t)row*288 + u*3;
        q[0]=o0; q[1]=o1; q[2]=o2;
    }
    __syncthreads();
    if (t < 12) {
        float s = 0.f;
        #pragma unroll
        for (int i = 0; i < 12; i++) { float v = sqp[t*12 + i]; s += v*v; }
        g_qn[row*12 + t] = s;
    } else if (t < 24) {
        int h = t - 12;
        float s = 0.f;
        #pragma unroll
        for (int i = 0; i < 12; i++) { float v = skp[h*12 + i]; s += v*v; }
        g_kn[row*12 + h] = s;
    }
}

// ---------------- P[b,h,q,k] --------------------------------------------------
__global__ __launch_bounds__(256) void attP_kernel(const float* __restrict__ head_w)
{
    int bh = blockIdx.z;
    int b = bh / 12, h = bh - b*12;
    int q0 = blockIdx.y * 64, k0 = blockIdx.x * 64;
    __shared__ float Qs[44][64];
    __shared__ float Ks[44][64];
    __shared__ float qns[64], kns[64];
    int tid = threadIdx.x;
    for (int i = tid; i < 2048; i += 256) {
        int r = i & 63, c = i >> 6;
        Qs[c][r] = CATT * g_q[((size_t)(b*512) + q0 + r)*384 + h*32 + c];
        Ks[c][r] =        g_k[((size_t)(b*512) + k0 + r)*384 + h*32 + c];
    }
    for (int i = tid; i < 768; i += 256) {
        int r = i & 63, j = i >> 6;
        Qs[32+j][r] = g_qps[((size_t)(b*512) + q0 + r)*144 + h*12 + j];
        Ks[32+j][r] = g_kp [((size_t)(b*512) + k0 + r)*144 + h*12 + j];
    }
    if (tid < 64)       qns[tid]     = g_qn[((size_t)(b*512) + q0 + tid)*12 + h];
    else if (tid < 128) kns[tid-64]  = g_kn[((size_t)(b*512) + k0 + tid-64)*12 + h];
    __syncthreads();

    int tx = tid & 15, ty = tid >> 4;
    float acc[4][4];
    #pragma unroll
    for (int i = 0; i < 4; i++)
        #pragma unroll
        for (int j = 0; j < 4; j++) acc[i][j] = 0.f;
    #pragma unroll
    for (int kk = 0; kk < 44; kk++) {
        float4 ra = *(const float4*)&Qs[kk][ty*4];
        float4 rb = *(const float4*)&Ks[kk][tx*4];
        acc[0][0] += ra.x*rb.x; acc[0][1] += ra.x*rb.y; acc[0][2] += ra.x*rb.z; acc[0][3] += ra.x*rb.w;
        acc[1][0] += ra.y*rb.x; acc[1][1] += ra.y*rb.y; acc[1][2] += ra.y*rb.z; acc[1][3] += ra.y*rb.w;
        acc[2][0] += ra.z*rb.x; acc[2][1] += ra.z*rb.y; acc[2][2] += ra.z*rb.z; acc[2][3] += ra.z*rb.w;
        acc[3][0] += ra.w*rb.x; acc[3][1] += ra.w*rb.y; acc[3][2] += ra.w*rb.z; acc[3][3] += ra.w*rb.w;
    }
    float gamma = log1pf(__expf(head_w[h]));
    float cg = C2 * gamma;
    #pragma unroll
    for (int i = 0; i < 4; i++) {
        int qq = ty*4 + i;
        float qn_ = qns[qq];
        float4 o;
        o.x = acc[i][0] - cg*(qn_ + kns[tx*4+0]);
        o.y = acc[i][1] - cg*(qn_ + kns[tx*4+1]);
        o.z = acc[i][2] - cg*(qn_ + kns[tx*4+2]);
        o.w = acc[i][3] - cg*(qn_ + kns[tx*4+3]);
        *(float4*)&g_P[((size_t)(b*12+h)*512 + q0 + qq)*512 + k0 + tx*4] = o;
    }
}

// ---------------- fused pair-bias + softmax (cp.async double-buffered) ------
__global__ __launch_bounds__(256) void logits_kernel(
    const float* __restrict__ z, const float* __restrict__ nzw,
    const float* __restrict__ wpair)
{
    extern __shared__ float smem[];
    float* wpnz = smem;               // 1536
    float* ls   = smem + 1536;        // 6144
    float* zsh  = smem + 7680;        // 2 x 512*18

    int row = blockIdx.x;
    int b = row >> 9, q = row & 511;
    int tid = threadIdx.x;
    const float* zq = z + ((size_t)(b*512 + q)) * 512 * 128;

    for (int j = tid; j < 4096; j += 256) {
        int k = j >> 3, c2 = j & 7;
        cpasync8(zsh + k*18 + c2*2, zq + (size_t)k*128 + c2*2);
    }
    CP_COMMIT();

    for (int i = tid; i < 1536; i += 256) {
        int c = i & 127;
        wpnz[i] = WL * wpair[i] * nzw[c];
    }
    for (int i = tid; i < 6144; i += 256) {
        int h = i >> 9, k = i & 511;
        ls[i] = g_P[((size_t)(b*12+h)*512 + q)*512 + k];
    }

    int k1 = tid, k2 = tid + 256;
    ull acc1[12], acc2[12], ssp1 = 0ull, ssp2 = 0ull;
    #pragma unroll
    for (int h = 0; h < 12; h++) { acc1[h] = 0ull; acc2[h] = 0ull; }

    for (int c0 = 0; c0 < 128; c0 += 16) {
        int buf = (c0 >> 4) & 1;
        if (c0 + 16 < 128) {
            float* dst = zsh + (buf^1)*9216;
            const float* src = zq + c0 + 16;
            for (int j = tid; j < 4096; j += 256) {
                int k = j >> 3, c2 = j & 7;
                cpasync8(dst + k*18 + c2*2, src + (size_t)k*128 + c2*2);
            }
            CP_COMMIT();
            CP_WAIT1();
        } else {
            CP_WAIT0();
        }
        __syncthreads();
        const float* zb = zsh + buf*9216;
        const ull* z1 = (const ull*)(zb + k1*18);
        const ull* z2 = (const ull*)(zb + k2*18);
        const ull* wp = (const ull*)wpnz;
        int wbase = c0 >> 1;
        #pragma unroll
        for (int cp = 0; cp < 8; cp++) {
            ull zp1 = z1[cp], zp2 = z2[cp];
            ssp1 = ffma2(zp1, zp1, ssp1);
            ssp2 = ffma2(zp2, zp2, ssp2);
            #pragma unroll
            for (int h = 0; h < 12; h++) {
                ull w = wp[h*64 + wbase + cp];
                acc1[h] = ffma2(zp1, w, acc1[h]);
                acc2[h] = ffma2(zp2, w, acc2[h]);
            }
        }
        __syncthreads();
    }
    {
        float ss1 = f2lo(ssp1) + f2hi(ssp1);
        float ss2 = f2lo(ssp2) + f2hi(ssp2);
        float r1 = rsqrtf(ss1 * (1.f/128.f) + 1e-6f);
        float r2 = rsqrtf(ss2 * (1.f/128.f) + 1e-6f);
        g_rsc[(size_t)row*512 + k1] = r1;
        g_rsc[(size_t)row*512 + k2] = r2;
        #pragma unroll
        for (int h = 0; h < 12; h++) {
            ls[h*512 + k1] += (f2lo(acc1[h]) + f2hi(acc1[h])) * r1;
            ls[h*512 + k2] += (f2lo(acc2[h]) + f2hi(acc2[h])) * r2;
        }
    }
    __syncthreads();

    int warp = tid >> 5, lane = tid & 31;
    for (int h = warp; h < 12; h += 8) {
        float m = -1e30f;
        for (int k = lane; k < 512; k += 32) m = fmaxf(m, ls[h*512 + k]);
        #pragma unroll
        for (int o = 16; o; o >>= 1) m = fmaxf(m, __shfl_xor_sync(0xffffffffu, m, o));
        float s = 0.f;
        for (int k = lane; k < 512; k += 32) {
            float e = __expf(ls[h*512 + k] - m);
            ls[h*512 + k] = e; s += e;
        }
        #pragma unroll
        for (int o = 16; o; o >>= 1) s += __shfl_xor_sync(0xffffffffu, s, o);
        float inv = 1.f / s;
        float* ao = g_att + ((size_t)(b*12 + h)*512 + q)*512;
        for (int k = lane; k < 512; k += 32) ao[k] = ls[h*512 + k] * inv;
    }
}

// ---------------- o = a@v, op_global = a@vp ----------------------------------
__global__ __launch_bounds__(256) void o_op_kernel()
{
    int bh = blockIdx.y;
    int b = bh / 12, h = bh - b*12;
    int q0 = blockIdx.x * 64;
    __shared__ float A_sh[64*65];
    __shared__ float Vs[64][57];
    int tid = threadIdx.x;
    int cgrp = tid >> 5;
    int l    = tid & 31;
    float acc[2][7];
    #pragma unroll
    for (int i = 0; i < 2; i++)
        #pragma unroll
        for (int j = 0; j < 7; j++) acc[i][j] = 0.f;

    for (int k0 = 0; k0 < 512; k0 += 64) {
        __syncthreads();
        for (int j = tid; j < 4096; j += 256) {
            int kk = j & 63, r = j >> 6;
            A_sh[r*65 + kk] = g_att[((size_t)(b*12+h)*512 + q0 + r)*512 + k0 + kk];
        }
        for (int j = tid; j < 2048; j += 256) {
            int kk = j >> 5, c = j & 31;
            Vs[kk][c] = g_v[((size_t)(b*512) + k0 + kk)*384 + h*32 + c];
        }
        for (int j = tid; j < 1536; j += 256) {
            int kk = j / 24, c = j - kk*24;
            Vs[kk][32 + c] = g_vp[((size_t)(b*512) + k0 + kk)*288 + h*24 + c];
        }
        __syncthreads();
        #pragma unroll 4
        for (int kk = 0; kk < 64; kk++) {
            float a0 = A_sh[(l*2)*65 + kk];
            float a1 = A_sh[(l*2+1)*65 + kk];
            #pragma unroll
            for (int j = 0; j < 7; j++) {
                float vv = Vs[kk][cgrp*7 + j];
                acc[0][j] += a0 * vv;
                acc[1][j] += a1 * vv;
            }
        }
    }
    #pragma unroll
    for (int i = 0; i < 2; i++) {
        size_t row = (size_t)(b*512) + q0 + l*2 + i;
        #pragma unroll
        for (int j = 0; j < 7; j++) {
            int c = cgrp*7 + j;
            if (c < 32) g_cat[row*cCAT + h*32 + c] = acc[i][j];
            else        g_opg[row*288 + h*24 + (c - 32)] = acc[i][j];
        }
    }
}

// ---------------- op epilogue ------------------------------------------------
__global__ __launch_bounds__(96) void op_epilogue_kernel(
    const float* __restrict__ rot, const float* __restrict__ trans)
{
    int row = blockIdx.x;
    __shared__ float R[9], T[3];
    int t = threadIdx.x;
    if (t < 9) R[t] = rot[(size_t)row*9 + t];
    if (t >= 9 && t < 12) T[t-9] = trans[(size_t)row*3 + (t-9)];
    __syncthreads();
    const float* pt = g_opg + (size_t)row*288 + t*3;
    float v0 = pt[0] - T[0];
    float v1 = pt[1] - T[1];
    float v2 = pt[2] - T[2];
    float l0 = R[0]*v0 + R[3]*v1 + R[6]*v2;
    float l1 = R[1]*v0 + R[4]*v1 + R[7]*v2;
    float l2 = R[2]*v0 + R[5]*v1 + R[8]*v2;
    float* cb = g_cat + (size_t)row * cCAT;
    cb[384 + t*3]     = l0;
    cb[384 + t*3 + 1] = l1;
    cb[384 + t*3 + 2] = l2;
    cb[672 + t] = sqrtf(l0*l0 + l1*l1 + l2*l2 + 1e-8f);
}

// ---------------- opair = (a*rsc) @ z, * nzw (cp.async double-buffered) -----
__global__ __launch_bounds__(256) void opair_kernel(
    const float* __restrict__ z, const float* __restrict__ nzw)
{
    int row = blockIdx.x;
    int b = row >> 9, q = row & 511;
    __shared__ float a_sh[12*512];
    __shared__ __align__(16) float zt[2][16][132];
    __shared__ float rsc_sh[512];
    __shared__ float nzw_sh[128];
    int tid = threadIdx.x;
    const float* zq = z + ((size_t)(b*512 + q)) * 512 * 128;

    for (int j = tid; j < 512; j += 256) {
        int r = j >> 5, c4 = j & 31;
        cpasync16(&zt[0][r][c4*4], zq + (size_t)r*128 + c4*4);
    }
    CP_COMMIT();

    if (tid < 128) nzw_sh[tid] = nzw[tid];
    rsc_sh[tid]       = g_rsc[(size_t)row*512 + tid];
    rsc_sh[tid + 256] = g_rsc[(size_t)row*512 + tid + 256];
    __syncthreads();
    for (int i = tid; i < 6144; i += 256) {
        int h = i >> 9, k = i & 511;
        a_sh[i] = g_att[((size_t)(b*12+h)*512 + q)*512 + k] * rsc_sh[k];
    }

    int h0 = tid >> 5, c40 = tid & 31;
    int idx1 = tid + 256;
    int h1 = idx1 >> 5, c41 = idx1 & 31;
    ull acc0a = 0ull, acc0b = 0ull, acc1a = 0ull, acc1b = 0ull;

    for (int k0 = 0; k0 < 512; k0 += 16) {
        int buf = (k0 >> 4) & 1;
        if (k0 + 16 < 512) {
            const float* src = zq + (size_t)(k0 + 16)*128;
            for (int j = tid; j < 512; j += 256) {
                int r = j >> 5, c4 = j & 31;
                cpasync16(&zt[buf^1][r][c4*4], src + (size_t)r*128 + c4*4);
            }
            CP_COMMIT();
            CP_WAIT1();
        } else {
            CP_WAIT0();
        }
        __syncthreads();
        #pragma unroll 4
        for (int kk = 0; kk < 16; kk++) {
            int kg = k0 + kk;
            ull a0 = dup2(a_sh[h0*512 + kg]);
            const ull* zp = (const ull*)&zt[buf][kk][c40*4];
            acc0a = ffma2(a0, zp[0], acc0a);
            acc0b = ffma2(a0, zp[1], acc0b);
            if (tid < 128) {
                ull a1 = dup2(a_sh[h1*512 + kg]);
                const ull* zw = (const ull*)&zt[buf][kk][c41*4];
                acc1a = ffma2(a1, zw[0], acc1a);
                acc1b = ffma2(a1, zw[1], acc1b);
            }
        }
        __syncthreads();
    }
    float* cb = g_cat + (size_t)row * cCAT + 768;
    float4 o0;
    o0.x = f2lo(acc0a) * nzw_sh[c40*4+0];
    o0.y = f2hi(acc0a) * nzw_sh[c40*4+1];
    o0.z = f2lo(acc0b) * nzw_sh[c40*4+2];
    o0.w = f2hi(acc0b) * nzw_sh[c40*4+3];
    *(float4*)&cb[tid*4] = o0;
    if (tid < 128) {
        float4 o1;
        o1.x = f2lo(acc1a) * nzw_sh[c41*4+0];
        o1.y = f2hi(acc1a) * nzw_sh[c41*4+1];
        o1.z = f2lo(acc1b) * nzw_sh[c41*4+2];
        o1.w = f2hi(acc1b) * nzw_sh[c41*4+3];
        *(float4*)&cb[idx1*4] = o1;
    }
}

// ---------------- frame update ----------------------------------------------
__global__ __launch_bounds__(192) void frame_kernel(
    const float* __restrict__ w_frame,
    const float* __restrict__ rot, const float* __restrict__ trans,
    float* __restrict__ out_rot, float* __restrict__ out_trans)
{
    int row = blockIdx.x;
    __shared__ float xs[384];
    __shared__ float v6[6];
    int t = threadIdx.x;
    xs[t]       = g_x3[(size_t)row*384 + t];
    xs[t + 192] = g_x3[(size_t)row*384 + t + 192];
    __syncthreads();
    int w = t >> 5, lane = t & 31;
    {
        const float* wf = w_frame + w*384;
        float acc = 0.f;
        for (int i = lane; i < 384; i += 32) acc += xs[i] * wf[i];
        #pragma unroll
        for (int o = 16; o; o >>= 1) acc += __shfl_xor_sync(0xffffffffu, acc, o);
        if (lane == 0) v6[w] = acc;
    }
    __syncthreads();
    if (t == 0) {
        float a = v6[0], bq = v6[1], cq = v6[2];
        float nq = rsqrtf(1.f + a*a + bq*bq + cq*cq);
        float qw = nq, qx = a*nq, qy = bq*nq, qz = cq*nq;
        float Ru[9];
        Ru[0] = 1.f - 2.f*(qy*qy + qz*qz); Ru[1] = 2.f*(qx*qy - qw*qz); Ru[2] = 2.f*(qx*qz + qw*qy);
        Ru[3] = 2.f*(qx*qy + qw*qz); Ru[4] = 1.f - 2.f*(qx*qx + qz*qz); Ru[5] = 2.f*(qy*qz - qw*qx);
        Ru[6] = 2.f*(qx*qz - qw*qy); Ru[7] = 2.f*(qy*qz + qw*qx); Ru[8] = 1.f - 2.f*(qx*qx + qy*qy);
        const float* R = rot + (size_t)row*9;
        #pragma unroll
        for (int i = 0; i < 3; i++)
            #pragma unroll
            for (int kcol = 0; kcol < 3; kcol++)
                out_rot[(size_t)row*9 + i*3 + kcol] =
                    R[i*3+0]*Ru[0*3+kcol] + R[i*3+1]*Ru[1*3+kcol] + R[i*3+2]*Ru[2*3+kcol];
        #pragma unroll
        for (int i = 0; i < 3; i++)
            out_trans[(size_t)row*3 + i] =
                R[i*3+0]*v6[3] + R[i*3+1]*v6[4] + R[i*3+2]*v6[5] + trans[(size_t)row*3 + i];
    }
}

// ---------------- host orchestration ----------------------------------------
extern "C" void kernel_launch(void* const* d_in, const int* in_sizes, int n_in,
                              void* d_out, int out_size)
{
    (void)in_sizes; (void)n_in; (void)out_size;
    const float* s       = (const float*)d_in[0];
    const float* rot     = (const float*)d_in[1];
    const float* trans   = (const float*)d_in[2];
    const float* z       = (const float*)d_in[3];
    const float* nzw     = (const float*)d_in[5];
    const float* n1      = (const float*)d_in[6];
    const float* n2      = (const float*)d_in[7];
    const float* n3      = (const float*)d_in[8];
    const float* w_qkv   = (const float*)d_in[9];
    const float* w_qpts  = (const float*)d_in[10];
    const float* w_kpts  = (const float*)d_in[11];
    const float* w_vpts  = (const float*)d_in[12];
    const float* head_w  = (const float*)d_in[13];
    const float* w_pair  = (const float*)d_in[14];
    const float* w_out   = (const float*)d_in[15];
    const float* w12     = (const float*)d_in[16];
    const float* w3      = (const float*)d_in[17];
    const float* w_frame = (const float*)d_in[18];

    float* out       = (float*)d_out;
    float* out_s     = out;
    float* out_rot   = out + (size_t)cBN * cCS;
    float* out_trans = out_rot + (size_t)cBN * 9;

    float *p_s0, *p_wcat, *p_proj, *p_cat, *p_s1, *p_x, *p_hh, *p_x3, *p_part;
    unsigned *p_ahi, *p_alo, *p_whi, *p_wlo;
    cudaGetSymbolAddress((void**)&p_s0,   g_s0);
    cudaGetSymbolAddress((void**)&p_wcat, g_wcat);
    cudaGetSymbolAddress((void**)&p_proj, g_proj);
    cudaGetSymbolAddress((void**)&p_cat,  g_cat);
    cudaGetSymbolAddress((void**)&p_s1,   g_s1);
    cudaGetSymbolAddress((void**)&p_x,    g_x);
    cudaGetSymbolAddress((void**)&p_hh,   g_hh);
    cudaGetSymbolAddress((void**)&p_x3,   g_x3);
    cudaGetSymbolAddress((void**)&p_part, g_part);
    cudaGetSymbolAddress((void**)&p_ahi,  g_ahi);
    cudaGetSymbolAddress((void**)&p_alo,  g_alo);
    cudaGetSymbolAddress((void**)&p_whi,  g_whi);
    cudaGetSymbolAddress((void**)&p_wlo,  g_wlo);

    static cudaStream_t sW = 0, sA = 0;
    static cudaEvent_t evF = 0, evW1 = 0, evW2 = 0, evF2 = 0, evA = 0;
    if (!sW) {
        cudaFuncSetAttribute(logits_kernel,
            cudaFuncAttributeMaxDynamicSharedMemorySize, 104448);
        cudaStreamCreate(&sW);
        cudaStreamCreate(&sA);
        cudaEventCreateWithFlags(&evF,  cudaEventDisableTiming);
        cudaEventCreateWithFlags(&evW1, cudaEventDisableTiming);
        cudaEventCreateWithFlags(&evW2, cudaEventDisableTiming);
        cudaEventCreateWithFlags(&evF2, cudaEventDisableTiming);
        cudaEventCreateWithFlags(&evA,  cudaEventDisableTiming);
    }

    // ---- fork: weight preprocessing (depends only on inputs) on sW ---------
    cudaEventRecord(evF, 0);
    cudaStreamWaitEvent(sW, evF, 0);
    wcat_kernel<<<648, 256, 0, sW>>>(w_qkv, w_qpts, w_kpts, w_vpts);
    split_t_kernel<<<dim3(27,6), 256, 0, sW>>>(p_wcat, p_whi+OFF_WCAT, p_wlo+OFF_WCAT, 384, 1728);
    cudaEventRecord(evW1, sW);
    split_t_kernel<<<dim3(6,36), 256, 0, sW>>>(w_out, p_whi+OFF_WOUT, p_wlo+OFF_WOUT, 2304, 384);
    split_t_kernel<<<dim3(48,6), 256, 0, sW>>>(w12, p_whi+OFF_W12, p_wlo+OFF_W12, 384, 3072);
    split_t_kernel<<<dim3(6,24), 256, 0, sW>>>(w3, p_whi+OFF_W3, p_wlo+OFF_W3, 1536, 384);
    cudaEventRecord(evW2, sW);

    // ---- main chain ---------------------------------------------------------
    rmsnorm_kernel<<<cBN, 128>>>(s, n1, p_s0, cCS);
    split_t_kernel<<<dim3(16,6), 256>>>(p_s0, p_ahi, p_alo, 384, 1024);
    cudaStreamWaitEvent(0, evW1, 0);
    gemm_bf16_kernel<<<dim3(27,8,1), 128>>>(p_ahi, p_alo, p_whi+OFF_WCAT, p_wlo+OFF_WCAT,
                                            nullptr, p_proj, 1728, 192);
    rope_points_kernel<<<cBN, 384>>>(rot, trans, head_w);
    attP_kernel<<<dim3(8,8,24), 256>>>(head_w);
    logits_kernel<<<cBN, 256, 104448>>>(z, nzw, w_pair);

    // ---- fork: o_op chain on sA concurrent with opair -----------------------
    cudaEventRecord(evF2, 0);
    cudaStreamWaitEvent(sA, evF2, 0);
    o_op_kernel<<<dim3(8,24), 256, 0, sA>>>();
    op_epilogue_kernel<<<cBN, 96, 0, sA>>>(rot, trans);
    cudaEventRecord(evA, sA);
    opair_kernel<<<cBN, 256>>>(z, nzw);
    cudaStreamWaitEvent(0, evA, 0);

    // ---- output projection + FFN -------------------------------------------
    split_t_kernel<<<dim3(16,36), 256>>>(p_cat, p_ahi, p_alo, 2304, 1024);
    cudaStreamWaitEvent(0, evW2, 0);
    gemm_bf16_kernel<<<dim3(6,8,4), 128>>>(p_ahi, p_alo, p_whi+OFF_WOUT, p_wlo+OFF_WOUT,
                                           nullptr, p_part, 384, 288);
    combine4_rms_kernel<<<cBN, 128>>>(s, n2, p_s1, p_x);
    split_t_kernel<<<dim3(16,6), 256>>>(p_x, p_ahi, p_alo, 384, 1024);
    gemm_bf16_kernel<<<dim3(48,8,1), 128>>>(p_ahi, p_alo, p_whi+OFF_W12, p_wlo+OFF_W12,
                                            nullptr, p_hh, 3072, 192);
    split_gated_t_kernel<<<dim3(16,24), 256>>>(p_ahi, p_alo);
    gemm_bf16_kernel<<<dim3(6,8,4), 128>>>(p_ahi, p_alo, p_whi+OFF_W3, p_wlo+OFF_W3,
                                           nullptr, p_part, 384, 192);
    combine4_rms_kernel<<<cBN, 128>>>(p_s1, n3, out_s, p_x3);
    frame_kernel<<<cBN, 192>>>(w_frame, rot, trans, out_rot, out_trans);
}

// round 17
// speedup vs baseline: 1.0130x; 1.0130x over previous
#include <cuda_runtime.h>
#include <cuda_bf16.h>
#include <math.h>
#include <stdint.h>

typedef unsigned long long ull;

// Problem constants (fixed by setup_inputs)
static const int cB  = 2;
static const int cN  = 512;
static const int cCS = 384;
static const int cCZ = 128;
static const int cH  = 12;
static const int cCH = 32;
static const int cPQ = 4;
static const int cPV = 8;
static const int cHID = 1536;
static const int cBN = 1024;
static const int cCAT = 2304;
static const int cPROJ = 1728;

#define WL   0.5773502691896258f
#define WCC  0.23570226039551584f
#define C2   (0.5f*WL*WCC)
#define CATT (WL*0.17677669529663687f)

// weight-split arena offsets (u32 units)
#define OFF_WCAT 0
#define OFF_WOUT 331776
#define OFF_W12  774144
#define OFF_W3   1363968
#define W_ARENA  1658880

// ---------------- scratch (device globals) ----------------------------------
__device__ float g_wcat [cPROJ*cCS];
__device__ float g_s0   [cBN*cCS];
__device__ float g_proj [cBN*cPROJ];
__device__ float g_q    [cBN*cH*cCH];
__device__ float g_k    [cBN*cH*cCH];
__device__ float g_v    [cBN*cH*cCH];
__device__ float g_qps  [cBN*cH*cPQ*3];
__device__ float g_kp   [cBN*cH*cPQ*3];
__device__ float g_vp   [cBN*cH*cPV*3];
__device__ float g_qn   [cBN*cH];
__device__ float g_kn   [cBN*cH];
__device__ float g_P    [(size_t)cB*cH*cN*cN];
__device__ float g_att  [(size_t)cB*cH*cN*cN];
__device__ float g_opg  [cBN*cH*cPV*3];
__device__ float g_cat  [cBN*cCAT];
__device__ float g_s1   [cBN*cCS];
__device__ float g_x    [cBN*cCS];
__device__ float g_hh   [cBN*2*cHID];
__device__ float g_x3   [cBN*cCS];
__device__ float g_part [4*cBN*cCS];
// split-bf16 packed operand buffers
__device__ unsigned g_ahi[1152*1024];
__device__ unsigned g_alo[1152*1024];
__device__ unsigned g_whi[W_ARENA];
__device__ unsigned g_wlo[W_ARENA];

// packed fp32x2 helpers (Blackwell)
__device__ __forceinline__ ull ffma2(ull a, ull b, ull c) {
    ull d;
    asm("fma.rn.f32x2 %0, %1, %2, %3;" : "=l"(d) : "l"(a), "l"(b), "l"(c));
    return d;
}
__device__ __forceinline__ ull dup2(float v) {
    ull d; unsigned u = __float_as_uint(v);
    asm("mov.b64 %0, {%1, %1};" : "=l"(d) : "r"(u));
    return d;
}
__device__ __forceinline__ float f2lo(ull p){ return __uint_as_float((unsigned)p); }
__device__ __forceinline__ float f2hi(ull p){ return __uint_as_float((unsigned)(p>>32)); }

// cp.async helpers
__device__ __forceinline__ void cpasync8(void* smem, const void* gmem) {
    unsigned s = (unsigned)__cvta_generic_to_shared(smem);
    asm volatile("cp.async.ca.shared.global [%0], [%1], 8;" :: "r"(s), "l"(gmem));
}
__device__ __forceinline__ void cpasync16(void* smem, const void* gmem) {
    unsigned s = (unsigned)__cvta_generic_to_shared(smem);
    asm volatile("cp.async.cg.shared.global [%0], [%1], 16;" :: "r"(s), "l"(gmem));
}
#define CP_COMMIT() asm volatile("cp.async.commit_group;")
#define CP_WAIT1()  asm volatile("cp.async.wait_group 1;")
#define CP_WAIT0()  asm volatile("cp.async.wait_group 0;")

// bf16 split-pack
__device__ __forceinline__ void splitpack(float x, float y, unsigned &hi, unsigned &lo) {
    __nv_bfloat16 xh = __float2bfloat16(x), yh = __float2bfloat16(y);
    float xr = x - __bfloat162float(xh), yr = y - __bfloat162float(yh);
    __nv_bfloat16 xl = __float2bfloat16(xr), yl = __float2bfloat16(yr);
    hi = (unsigned)__bfloat16_as_ushort(xh) | ((unsigned)__bfloat16_as_ushort(yh) << 16);
    lo = (unsigned)__bfloat16_as_ushort(xl) | ((unsigned)__bfloat16_as_ushort(yl) << 16);
}

// m16n8k16 bf16 MMA
__device__ __forceinline__ void mma16816(float* d, const unsigned* a, unsigned b0, unsigned b1) {
    asm("mma.sync.aligned.m16n8k16.row.col.f32.bf16.bf16.f32 "
        "{%0,%1,%2,%3}, {%4,%5,%6,%7}, {%8,%9}, {%0,%1,%2,%3};"
        : "+f"(d[0]), "+f"(d[1]), "+f"(d[2]), "+f"(d[3])
        : "r"(a[0]), "r"(a[1]), "r"(a[2]), "r"(a[3]), "r"(b0), "r"(b1));
}

// ---------------- RMSNorm ----------------------------------------------------
__global__ __launch_bounds__(128) void rmsnorm_kernel(
    const float* __restrict__ in, const float* __restrict__ w,
    float* __restrict__ out, int C)
{
    int row = blockIdx.x;
    const float* x = in + (size_t)row * C;
    float ss = 0.f;
    for (int i = threadIdx.x; i < C; i += 128) { float v = x[i]; ss += v*v; }
    __shared__ float red[4];
    #pragma unroll
    for (int o = 16; o; o >>= 1) ss += __shfl_xor_sync(0xffffffffu, ss, o);
    if ((threadIdx.x & 31) == 0) red[threadIdx.x >> 5] = ss;
    __syncthreads();
    float tot = red[0] + red[1] + red[2] + red[3];
    float r = rsqrtf(tot / (float)C + 1e-6f);
    float* o2 = out + (size_t)row * C;
    for (int i = threadIdx.x; i < C; i += 128) o2[i] = x[i] * r * w[i];
}

// ---------------- fused: sum 4 split-K partials + resid -> Cs; rmsnorm -> Cx -
__global__ __launch_bounds__(128) void combine4_rms_kernel(
    const float* __restrict__ resid, const float* __restrict__ w,
    float* __restrict__ Cs, float* __restrict__ Cx)
{
    int row = blockIdx.x;
    int t = threadIdx.x;
    float vals[3];
    float ss = 0.f;
    #pragma unroll
    for (int i = 0; i < 3; i++) {
        int c = t + i*128;
        size_t idx = (size_t)row*384 + c;
        float v = g_part[idx] + g_part[idx + 393216] + g_part[idx + 786432]
                + g_part[idx + 1179648] + resid[idx];
        vals[i] = v; ss += v*v;
    }
    __shared__ float red[4];
    #pragma unroll
    for (int o = 16; o; o >>= 1) ss += __shfl_xor_sync(0xffffffffu, ss, o);
    if ((t & 31) == 0) red[t >> 5] = ss;
    __syncthreads();
    float tot = red[0] + red[1] + red[2] + red[3];
    float r = rsqrtf(tot * (1.f/384.f) + 1e-6f);
    #pragma unroll
    for (int i = 0; i < 3; i++) {
        int c = t + i*128;
        size_t idx = (size_t)row*384 + c;
        Cs[idx] = vals[i];
        Cx[idx] = vals[i] * r * w[c];
    }
}

// ---------------- concat projection weights ---------------------------------
__global__ __launch_bounds__(256) void wcat_kernel(
    const float* __restrict__ wq, const float* __restrict__ wqp,
    const float* __restrict__ wkp, const float* __restrict__ wvp)
{
    int i = blockIdx.x * 256 + threadIdx.x;
    if (i >= cPROJ * 96) return;
    int row = i / 96, c4 = i - row * 96;
    float4 v;
    if      (row < 1152) v = ((const float4*)wq )[(size_t)row*96 + c4];
    else if (row < 1296) v = ((const float4*)wqp)[(size_t)(row-1152)*96 + c4];
    else if (row < 1440) v = ((const float4*)wkp)[(size_t)(row-1296)*96 + c4];
    else                 v = ((const float4*)wvp)[(size_t)(row-1440)*96 + c4];
    ((float4*)g_wcat)[i] = v;
}

// ---------------- tiled transpose + bf16 split ------------------------------
__global__ __launch_bounds__(256) void split_t_kernel(
    const float* __restrict__ A, unsigned* __restrict__ Hi, unsigned* __restrict__ Lo,
    int K, int outStride)
{
    __shared__ float tile[64][65];
    int r0 = blockIdx.x * 64;
    int k0 = blockIdx.y * 64;
    int tid = threadIdx.x;
    #pragma unroll
    for (int i = 0; i < 4; i++) {
        int l = tid + i*256;
        int r = l >> 4, c4 = (l & 15)*4;
        float4 v = *(const float4*)(A + (size_t)(r0 + r)*K + k0 + c4);
        tile[r][c4+0]=v.x; tile[r][c4+1]=v.y; tile[r][c4+2]=v.z; tile[r][c4+3]=v.w;
    }
    __syncthreads();
    int kp0 = k0 >> 1;
    #pragma unroll
    for (int i = 0; i < 8; i++) {
        int l = tid + i*256;
        int kp = l >> 6, r = l & 63;
        unsigned hi, lo;
        splitpack(tile[r][kp*2], tile[r][kp*2+1], hi, lo);
        Hi[(size_t)(kp0+kp)*outStride + r0 + r] = hi;
        Lo[(size_t)(kp0+kp)*outStride + r0 + r] = lo;
    }
}

// gated variant
__global__ __launch_bounds__(256) void split_gated_t_kernel(
    unsigned* __restrict__ Hi, unsigned* __restrict__ Lo)
{
    __shared__ float tile[64][65];
    int r0 = blockIdx.x * 64;
    int k0 = blockIdx.y * 64;
    int tid = threadIdx.x;
    #pragma unroll
    for (int i = 0; i < 4; i++) {
        int l = tid + i*256;
        int r = l >> 4, c4 = (l & 15)*4;
        const float* base = g_hh + (size_t)(r0 + r)*3072 + k0 + c4;
        float4 a = *(const float4*)base;
        float4 b = *(const float4*)(base + 1536);
        tile[r][c4+0] = (a.x / (1.f + __expf(-a.x))) * b.x;
        tile[r][c4+1] = (a.y / (1.f + __expf(-a.y))) * b.y;
        tile[r][c4+2] = (a.z / (1.f + __expf(-a.z))) * b.z;
        tile[r][c4+3] = (a.w / (1.f + __expf(-a.w))) * b.w;
    }
    __syncthreads();
    int kp0 = k0 >> 1;
    #pragma unroll
    for (int i = 0; i < 8; i++) {
        int l = tid + i*256;
        int kp = l >> 6, r = l & 63;
        unsigned hi, lo;
        splitpack(tile[r][kp*2], tile[r][kp*2+1], hi, lo);
        Hi[(size_t)(kp0+kp)*1024 + r0 + r] = hi;
        Lo[(size_t)(kp0+kp)*1024 + r0 + r] = lo;
    }
}

// ---------------- bf16x3 tensor-core GEMM (cp.async double-buffered) --------
__global__ __launch_bounds__(128) void gemm_bf16_kernel(
    const unsigned* __restrict__ Ahi, const unsigned* __restrict__ Alo,
    const unsigned* __restrict__ Whi, const unsigned* __restrict__ Wlo,
    const float* __restrict__ resid, float* __restrict__ C,
    int Nn, int kpPer)
{
    __shared__ __align__(16) unsigned sAh[2][16][136], sAl[2][16][136];
    __shared__ __align__(16) unsigned sBh[2][16][72],  sBl[2][16][72];
    int bm = blockIdx.y * 128, bn = blockIdx.x * 64;
    int kp0 = blockIdx.z * kpPer;
    float* Cout = C + (size_t)blockIdx.z * 1024 * Nn;
    const float* rz = (gridDim.z == 1) ? resid : nullptr;

    int tid = threadIdx.x, wid = tid >> 5, lane = tid & 31;
    int quad = lane >> 2, tid4 = lane & 3;
    int wm = (wid & 1) * 64, wn = (wid >> 1) * 32;

    float acc[4][4][4];
    #pragma unroll
    for (int a = 0; a < 4; a++)
        #pragma unroll
        for (int b = 0; b < 4; b++)
            #pragma unroll
            for (int c = 0; c < 4; c++) acc[a][b][c] = 0.f;

    int la_r = tid >> 5, la_c4 = (tid & 31)*4;
    int lb_r = tid >> 4, lb_c4 = (tid & 15)*4;
    #define LOAD_CHUNK(kc, buf) do {                                            \
        _Pragma("unroll")                                                       \
        for (int i = 0; i < 4; i++) {                                           \
            int r = la_r + i*4;                                                 \
            size_t off = (size_t)(kp0+(kc)+r)*1024 + bm + la_c4;                \
            cpasync16(&sAh[buf][r][la_c4], Ahi + off);                          \
            cpasync16(&sAl[buf][r][la_c4], Alo + off);                          \
        }                                                                       \
        _Pragma("unroll")                                                       \
        for (int i = 0; i < 2; i++) {                                           \
            int r = lb_r + i*8;                                                 \
            size_t off = (size_t)(kp0+(kc)+r)*Nn + bn + lb_c4;                  \
            cpasync16(&sBh[buf][r][lb_c4], Whi + off);                          \
            cpasync16(&sBl[buf][r][lb_c4], Wlo + off);                          \
        }                                                                       \
        CP_COMMIT();                                                            \
    } while (0)

    LOAD_CHUNK(0, 0);

    for (int kc = 0; kc < kpPer; kc += 16) {
        int buf = (kc >> 4) & 1;
        if (kc + 16 < kpPer) {
            LOAD_CHUNK(kc + 16, buf^1);
            CP_WAIT1();
        } else {
            CP_WAIT0();
        }
        __syncthreads();
        #pragma unroll
        for (int step = 0; step < 2; step++) {
            int kb = step*8;
            unsigned ah[4][4], al[4][4];
            #pragma unroll
            for (int mt = 0; mt < 4; mt++) {
                int m = wm + mt*16 + quad;
                ah[mt][0] = sAh[buf][kb+tid4][m];
                ah[mt][1] = sAh[buf][kb+tid4][m+8];
                ah[mt][2] = sAh[buf][kb+tid4+4][m];
                ah[mt][3] = sAh[buf][kb+tid4+4][m+8];
                al[mt][0] = sAl[buf][kb+tid4][m];
                al[mt][1] = sAl[buf][kb+tid4][m+8];
                al[mt][2] = sAl[buf][kb+tid4+4][m];
                al[mt][3] = sAl[buf][kb+tid4+4][m+8];
            }
            #pragma unroll
            for (int nt = 0; nt < 4; nt++) {
                int n = wn + nt*8 + quad;
                unsigned bh0 = sBh[buf][kb+tid4][n], bh1 = sBh[buf][kb+tid4+4][n];
                unsigned bl0 = sBl[buf][kb+tid4][n], bl1 = sBl[buf][kb+tid4+4][n];
                #pragma unroll
                for (int mt = 0; mt < 4; mt++) {
                    mma16816(acc[mt][nt], ah[mt], bh0, bh1);
                    mma16816(acc[mt][nt], ah[mt], bl0, bl1);
                    mma16816(acc[mt][nt], al[mt], bh0, bh1);
                }
            }
        }
        __syncthreads();
    }
    #pragma unroll
    for (int mt = 0; mt < 4; mt++) {
        #pragma unroll
        for (int nt = 0; nt < 4; nt++) {
            int r0 = bm + wm + mt*16 + quad;
            int cc = bn + wn + nt*8 + tid4*2;
            float2 v0 = make_float2(acc[mt][nt][0], acc[mt][nt][1]);
            float2 v1 = make_float2(acc[mt][nt][2], acc[mt][nt][3]);
            if (rz) {
                const float* p0 = rz + (size_t)r0*Nn + cc;
                const float* p1 = rz + (size_t)(r0+8)*Nn + cc;
                v0.x += p0[0]; v0.y += p0[1];
                v1.x += p1[0]; v1.y += p1[1];
            }
            *(float2*)(Cout + (size_t)r0*Nn + cc)     = v0;
            *(float2*)(Cout + (size_t)(r0+8)*Nn + cc) = v1;
        }
    }
}

// ---------------- merged: split qkv + RoPE + points -------------------------
__global__ __launch_bounds__(384) void rope_points_kernel(
    const float* __restrict__ rot, const float* __restrict__ trans,
    const float* __restrict__ head_w)
{
    int row = blockIdx.x;
    int n = row & (cN - 1);
    int t = threadIdx.x;
    const float* base = g_proj + (size_t)row * cPROJ;
    __shared__ float R[9], T[3];
    __shared__ float sqp[144], skp[144];

    g_v[(size_t)row * 384 + t] = base[768 + t];
    if (t < 9) R[t] = rot[(size_t)row*9 + t];
    if (t >= 9 && t < 12) T[t-9] = trans[(size_t)row*3 + (t-9)];
    if (t < 192) {
        int h = t / 16, c = t % 16;
        float inv = powf(10000.f, -(float)c / 16.f);
        float ang = (float)n * inv;
        float sn, cs;
        sincosf(ang, &sn, &cs);
        int i1 = h*32 + c, i2 = i1 + 16;
        float q1 = base[i1],     q2 = base[i2];
        float k1 = base[384+i1], k2 = base[384+i2];
        float* qo = g_q + (size_t)row * 384;
        float* ko = g_k + (size_t)row * 384;
        qo[i1] = q1*cs - q2*sn;  qo[i2] = q1*sn + q2*cs;
        ko[i1] = k1*cs - k2*sn;  ko[i2] = k1*sn + k2*cs;
    }
    __syncthreads();
    if (t < 48) {
        const float* p = base + 1152 + t*3;
        float o0 = R[0]*p[0] + R[1]*p[1] + R[2]*p[2] + T[0];
        float o1 = R[3]*p[0] + R[4]*p[1] + R[5]*p[2] + T[1];
        float o2 = R[6]*p[0] + R[7]*p[1] + R[8]*p[2] + T[2];
        int h = t >> 2;
        float gam = log1pf(__expf(head_w[h]));
        float s = 2.f * C2 * gam;
        float* q = g_qps + (size_t)row*144 + t*3;
        q[0]=o0*s; q[1]=o1*s; q[2]=o2*s;
        sqp[t*3]=o0; sqp[t*3+1]=o1; sqp[t*3+2]=o2;
    } else if (t < 96) {
        int u = t - 48;
        const float* p = base + 1296 + u*3;
        float o0 = R[0]*p[0] + R[1]*p[1] + R[2]*p[2] + T[0];
        float o1 = R[3]*p[0] + R[4]*p[1] + R[5]*p[2] + T[1];
        float o2 = R[6]*p[0] + R[7]*p[1] + R[8]*p[2] + T[2];
        float* q = g_kp + (size_t)row*144 + u*3;
        q[0]=o0; q[1]=o1; q[2]=o2;
        skp[u*3]=o0; skp[u*3+1]=o1; skp[u*3+2]=o2;
    } else if (t < 192) {
        int u = t - 96;
        const float* p = base + 1440 + u*3;
        float o0 = R[0]*p[0] + R[1]*p[1] + R[2]*p[2] + T[0];
        float o1 = R[3]*p[0] + R[4]*p[1] + R[5]*p[2] + T[1];
        float o2 = R[6]*p[0] + R[7]*p[1] + R[8]*p[2] + T[2];
        float* q = g_vp + (size_t)row*288 + u*3;
        q[0]=o0; q[1]=o1; q[2]=o2;
    }
    __syncthreads();
    if (t < 12) {
        float s = 0.f;
        #pragma unroll
        for (int i = 0; i < 12; i++) { float v = sqp[t*12 + i]; s += v*v; }
        g_qn[row*12 + t] = s;
    } else if (t < 24) {
        int h = t - 12;
        float s = 0.f;
        #pragma unroll
        for (int i = 0; i < 12; i++) { float v = skp[h*12 + i]; s += v*v; }
        g_kn[row*12 + h] = s;
    }
}

// ---------------- P[b,h,q,k] --------------------------------------------------
__global__ __launch_bounds__(256) void attP_kernel(const float* __restrict__ head_w)
{
    int bh = blockIdx.z;
    int b = bh / 12, h = bh - b*12;
    int q0 = blockIdx.y * 64, k0 = blockIdx.x * 64;
    __shared__ float Qs[44][64];
    __shared__ float Ks[44][64];
    __shared__ float qns[64], kns[64];
    int tid = threadIdx.x;
    for (int i = tid; i < 2048; i += 256) {
        int r = i & 63, c = i >> 6;
        Qs[c][r] = CATT * g_q[((size_t)(b*512) + q0 + r)*384 + h*32 + c];
        Ks[c][r] =        g_k[((size_t)(b*512) + k0 + r)*384 + h*32 + c];
    }
    for (int i = tid; i < 768; i += 256) {
        int r = i & 63, j = i >> 6;
        Qs[32+j][r] = g_qps[((size_t)(b*512) + q0 + r)*144 + h*12 + j];
        Ks[32+j][r] = g_kp [((size_t)(b*512) + k0 + r)*144 + h*12 + j];
    }
    if (tid < 64)       qns[tid]     = g_qn[((size_t)(b*512) + q0 + tid)*12 + h];
    else if (tid < 128) kns[tid-64]  = g_kn[((size_t)(b*512) + k0 + tid-64)*12 + h];
    __syncthreads();

    int tx = tid & 15, ty = tid >> 4;
    float acc[4][4];
    #pragma unroll
    for (int i = 0; i < 4; i++)
        #pragma unroll
        for (int j = 0; j < 4; j++) acc[i][j] = 0.f;
    #pragma unroll
    for (int kk = 0; kk < 44; kk++) {
        float4 ra = *(const float4*)&Qs[kk][ty*4];
        float4 rb = *(const float4*)&Ks[kk][tx*4];
        acc[0][0] += ra.x*rb.x; acc[0][1] += ra.x*rb.y; acc[0][2] += ra.x*rb.z; acc[0][3] += ra.x*rb.w;
        acc[1][0] += ra.y*rb.x; acc[1][1] += ra.y*rb.y; acc[1][2] += ra.y*rb.z; acc[1][3] += ra.y*rb.w;
        acc[2][0] += ra.z*rb.x; acc[2][1] += ra.z*rb.y; acc[2][2] += ra.z*rb.z; acc[2][3] += ra.z*rb.w;
        acc[3][0] += ra.w*rb.x; acc[3][1] += ra.w*rb.y; acc[3][2] += ra.w*rb.z; acc[3][3] += ra.w*rb.w;
    }
    float gamma = log1pf(__expf(head_w[h]));
    float cg = C2 * gamma;
    #pragma unroll
    for (int i = 0; i < 4; i++) {
        int qq = ty*4 + i;
        float qn_ = qns[qq];
        float4 o;
        o.x = acc[i][0] - cg*(qn_ + kns[tx*4+0]);
        o.y = acc[i][1] - cg*(qn_ + kns[tx*4+1]);
        o.z = acc[i][2] - cg*(qn_ + kns[tx*4+2]);
        o.w = acc[i][3] - cg*(qn_ + kns[tx*4+3]);
        *(float4*)&g_P[((size_t)(b*12+h)*512 + q0 + qq)*512 + k0 + tx*4] = o;
    }
}

// ------- fused pair-bias + softmax + opair (two pipelined z passes) ---------
__global__ __launch_bounds__(256) void logits_opair_kernel(
    const float* __restrict__ z, const float* __restrict__ nzw,
    const float* __restrict__ wpair)
{
    extern __shared__ float smem[];
    float* wpnz = smem;               // 1536
    float* ls   = smem + 1536;        // 6144 (logits -> att weights -> a*rsc)
    float* zsh  = smem + 7680;        // 18432: pass1: 2 x 512*18 ; pass2: 2 x 16*132
    __shared__ float rsc_sh[512];
    __shared__ float nzw_sh[128];

    int row = blockIdx.x;
    int b = row >> 9, q = row & 511;
    int tid = threadIdx.x;
    const float* zq = z + ((size_t)(b*512 + q)) * 512 * 128;

    // ---- pass 1 prefetch: z chunk c0=0 (all k, 16 channels) -----------------
    for (int j = tid; j < 4096; j += 256) {
        int k = j >> 3, c2 = j & 7;
        cpasync8(zsh + k*18 + c2*2, zq + (size_t)k*128 + c2*2);
    }
    CP_COMMIT();

    for (int i = tid; i < 1536; i += 256) {
        int c = i & 127;
        wpnz[i] = WL * wpair[i] * nzw[c];
    }
    if (tid < 128) nzw_sh[tid] = nzw[tid];
    for (int i = tid; i < 6144; i += 256) {
        int h = i >> 9, k = i & 511;
        ls[i] = g_P[((size_t)(b*12+h)*512 + q)*512 + k];
    }

    int k1 = tid, k2 = tid + 256;
    ull acc1[12], acc2[12], ssp1 = 0ull, ssp2 = 0ull;
    #pragma unroll
    for (int h = 0; h < 12; h++) { acc1[h] = 0ull; acc2[h] = 0ull; }

    for (int c0 = 0; c0 < 128; c0 += 16) {
        int buf = (c0 >> 4) & 1;
        if (c0 + 16 < 128) {
            float* dst = zsh + (buf^1)*9216;
            const float* src = zq + c0 + 16;
            for (int j = tid; j < 4096; j += 256) {
                int k = j >> 3, c2 = j & 7;
                cpasync8(dst + k*18 + c2*2, src + (size_t)k*128 + c2*2);
            }
            CP_COMMIT();
            CP_WAIT1();
        } else {
            CP_WAIT0();
        }
        __syncthreads();
        const float* zb = zsh + buf*9216;
        const ull* z1 = (const ull*)(zb + k1*18);
        const ull* z2 = (const ull*)(zb + k2*18);
        const ull* wp = (const ull*)wpnz;
        int wbase = c0 >> 1;
        #pragma unroll
        for (int cp = 0; cp < 8; cp++) {
            ull zp1 = z1[cp], zp2 = z2[cp];
            ssp1 = ffma2(zp1, zp1, ssp1);
            ssp2 = ffma2(zp2, zp2, ssp2);
            #pragma unroll
            for (int h = 0; h < 12; h++) {
                ull w = wp[h*64 + wbase + cp];
                acc1[h] = ffma2(zp1, w, acc1[h]);
                acc2[h] = ffma2(zp2, w, acc2[h]);
            }
        }
        __syncthreads();
    }
    {
        float ss1 = f2lo(ssp1) + f2hi(ssp1);
        float ss2 = f2lo(ssp2) + f2hi(ssp2);
        float r1 = rsqrtf(ss1 * (1.f/128.f) + 1e-6f);
        float r2 = rsqrtf(ss2 * (1.f/128.f) + 1e-6f);
        rsc_sh[k1] = r1;
        rsc_sh[k2] = r2;
        #pragma unroll
        for (int h = 0; h < 12; h++) {
            ls[h*512 + k1] += (f2lo(acc1[h]) + f2hi(acc1[h])) * r1;
            ls[h*512 + k2] += (f2lo(acc2[h]) + f2hi(acc2[h])) * r2;
        }
    }
    __syncthreads();

    // ---- softmax; write g_att; keep a*rsc in ls -----------------------------
    int warp = tid >> 5, lane = tid & 31;
    for (int h = warp; h < 12; h += 8) {
        float m = -1e30f;
        for (int k = lane; k < 512; k += 32) m = fmaxf(m, ls[h*512 + k]);
        #pragma unroll
        for (int o = 16; o; o >>= 1) m = fmaxf(m, __shfl_xor_sync(0xffffffffu, m, o));
        float s = 0.f;
        for (int k = lane; k < 512; k += 32) {
            float e = __expf(ls[h*512 + k] - m);
            ls[h*512 + k] = e; s += e;
        }
        #pragma unroll
        for (int o = 16; o; o >>= 1) s += __shfl_xor_sync(0xffffffffu, s, o);
        float inv = 1.f / s;
        float* ao = g_att + ((size_t)(b*12 + h)*512 + q)*512;
        for (int k = lane; k < 512; k += 32) {
            float a = ls[h*512 + k] * inv;
            ao[k] = a;
            ls[h*512 + k] = a * rsc_sh[k];   // pre-scaled for opair
        }
    }
    __syncthreads();

    // ---- pass 2: opair = (a*rsc) @ z, * nzw (reuse zsh as [2][16][132]) ----
    float* zt = zsh;
    for (int j = tid; j < 512; j += 256) {
        int r = j >> 5, c4 = j & 31;
        cpasync16(zt + r*132 + c4*4, zq + (size_t)r*128 + c4*4);
    }
    CP_COMMIT();

    int h0 = tid >> 5, c40 = tid & 31;
    int idx1 = tid + 256;
    int h1 = idx1 >> 5, c41 = idx1 & 31;
    ull acc0a = 0ull, acc0b = 0ull, acc1a = 0ull, acc1b = 0ull;

    for (int k0 = 0; k0 < 512; k0 += 16) {
        int buf = (k0 >> 4) & 1;
        if (k0 + 16 < 512) {
            float* dst = zt + (buf^1)*2112;
            const float* src = zq + (size_t)(k0 + 16)*128;
            for (int j = tid; j < 512; j += 256) {
                int r = j >> 5, c4 = j & 31;
                cpasync16(dst + r*132 + c4*4, src + (size_t)r*128 + c4*4);
            }
            CP_COMMIT();
            CP_WAIT1();
        } else {
            CP_WAIT0();
        }
        __syncthreads();
        const float* zb = zt + buf*2112;
        #pragma unroll 4
        for (int kk = 0; kk < 16; kk++) {
            int kg = k0 + kk;
            ull a0 = dup2(ls[h0*512 + kg]);
            const ull* zp = (const ull*)(zb + kk*132 + c40*4);
            acc0a = ffma2(a0, zp[0], acc0a);
            acc0b = ffma2(a0, zp[1], acc0b);
            if (tid < 128) {
                ull a1 = dup2(ls[h1*512 + kg]);
                const ull* zw = (const ull*)(zb + kk*132 + c41*4);
                acc1a = ffma2(a1, zw[0], acc1a);
                acc1b = ffma2(a1, zw[1], acc1b);
            }
        }
        __syncthreads();
    }
    float* cb = g_cat + (size_t)row * cCAT + 768;
    float4 o0;
    o0.x = f2lo(acc0a) * nzw_sh[c40*4+0];
    o0.y = f2hi(acc0a) * nzw_sh[c40*4+1];
    o0.z = f2lo(acc0b) * nzw_sh[c40*4+2];
    o0.w = f2hi(acc0b) * nzw_sh[c40*4+3];
    *(float4*)&cb[tid*4] = o0;
    if (tid < 128) {
        float4 o1;
        o1.x = f2lo(acc1a) * nzw_sh[c41*4+0];
        o1.y = f2hi(acc1a) * nzw_sh[c41*4+1];
        o1.z = f2lo(acc1b) * nzw_sh[c41*4+2];
        o1.w = f2hi(acc1b) * nzw_sh[c41*4+3];
        *(float4*)&cb[idx1*4] = o1;
    }
}

// ---------------- o = a@v, op_global = a@vp ----------------------------------
__global__ __launch_bounds__(256) void o_op_kernel()
{
    int bh = blockIdx.y;
    int b = bh / 12, h = bh - b*12;
    int q0 = blockIdx.x * 64;
    __shared__ float A_sh[64*65];
    __shared__ float Vs[64][57];
    int tid = threadIdx.x;
    int cgrp = tid >> 5;
    int l    = tid & 31;
    float acc[2][7];
    #pragma unroll
    for (int i = 0; i < 2; i++)
        #pragma unroll
        for (int j = 0; j < 7; j++) acc[i][j] = 0.f;

    for (int k0 = 0; k0 < 512; k0 += 64) {
        __syncthreads();
        for (int j = tid; j < 4096; j += 256) {
            int kk = j & 63, r = j >> 6;
            A_sh[r*65 + kk] = g_att[((size_t)(b*12+h)*512 + q0 + r)*512 + k0 + kk];
        }
        for (int j = tid; j < 2048; j += 256) {
            int kk = j >> 5, c = j & 31;
            Vs[kk][c] = g_v[((size_t)(b*512) + k0 + kk)*384 + h*32 + c];
        }
        for (int j = tid; j < 1536; j += 256) {
            int kk = j / 24, c = j - kk*24;
            Vs[kk][32 + c] = g_vp[((size_t)(b*512) + k0 + kk)*288 + h*24 + c];
        }
        __syncthreads();
        #pragma unroll 4
        for (int kk = 0; kk < 64; kk++) {
            float a0 = A_sh[(l*2)*65 + kk];
            float a1 = A_sh[(l*2+1)*65 + kk];
            #pragma unroll
            for (int j = 0; j < 7; j++) {
                float vv = Vs[kk][cgrp*7 + j];
                acc[0][j] += a0 * vv;
                acc[1][j] += a1 * vv;
            }
        }
    }
    #pragma unroll
    for (int i = 0; i < 2; i++) {
        size_t row = (size_t)(b*512) + q0 + l*2 + i;
        #pragma unroll
        for (int j = 0; j < 7; j++) {
            int c = cgrp*7 + j;
            if (c < 32) g_cat[row*cCAT + h*32 + c] = acc[i][j];
            else        g_opg[row*288 + h*24 + (c - 32)] = acc[i][j];
        }
    }
}

// ---------------- op epilogue ------------------------------------------------
__global__ __launch_bounds__(96) void op_epilogue_kernel(
    const float* __restrict__ rot, const float* __restrict__ trans)
{
    int row = blockIdx.x;
    __shared__ float R[9], T[3];
    int t = threadIdx.x;
    if (t < 9) R[t] = rot[(size_t)row*9 + t];
    if (t >= 9 && t < 12) T[t-9] = trans[(size_t)row*3 + (t-9)];
    __syncthreads();
    const float* pt = g_opg + (size_t)row*288 + t*3;
    float v0 = pt[0] - T[0];
    float v1 = pt[1] - T[1];
    float v2 = pt[2] - T[2];
    float l0 = R[0]*v0 + R[3]*v1 + R[6]*v2;
    float l1 = R[1]*v0 + R[4]*v1 + R[7]*v2;
    float l2 = R[2]*v0 + R[5]*v1 + R[8]*v2;
    float* cb = g_cat + (size_t)row * cCAT;
    cb[384 + t*3]     = l0;
    cb[384 + t*3 + 1] = l1;
    cb[384 + t*3 + 2] = l2;
    cb[672 + t] = sqrtf(l0*l0 + l1*l1 + l2*l2 + 1e-8f);
}

// ---------------- frame update ----------------------------------------------
__global__ __launch_bounds__(192) void frame_kernel(
    const float* __restrict__ w_frame,
    const float* __restrict__ rot, const float* __restrict__ trans,
    float* __restrict__ out_rot, float* __restrict__ out_trans)
{
    int row = blockIdx.x;
    __shared__ float xs[384];
    __shared__ float v6[6];
    int t = threadIdx.x;
    xs[t]       = g_x3[(size_t)row*384 + t];
    xs[t + 192] = g_x3[(size_t)row*384 + t + 192];
    __syncthreads();
    int w = t >> 5, lane = t & 31;
    {
        const float* wf = w_frame + w*384;
        float acc = 0.f;
        for (int i = lane; i < 384; i += 32) acc += xs[i] * wf[i];
        #pragma unroll
        for (int o = 16; o; o >>= 1) acc += __shfl_xor_sync(0xffffffffu, acc, o);
        if (lane == 0) v6[w] = acc;
    }
    __syncthreads();
    if (t == 0) {
        float a = v6[0], bq = v6[1], cq = v6[2];
        float nq = rsqrtf(1.f + a*a + bq*bq + cq*cq);
        float qw = nq, qx = a*nq, qy = bq*nq, qz = cq*nq;
        float Ru[9];
        Ru[0] = 1.f - 2.f*(qy*qy + qz*qz); Ru[1] = 2.f*(qx*qy - qw*qz); Ru[2] = 2.f*(qx*qz + qw*qy);
        Ru[3] = 2.f*(qx*qy + qw*qz); Ru[4] = 1.f - 2.f*(qx*qx + qz*qz); Ru[5] = 2.f*(qy*qz - qw*qx);
        Ru[6] = 2.f*(qx*qz - qw*qy); Ru[7] = 2.f*(qy*qz + qw*qx); Ru[8] = 1.f - 2.f*(qx*qx + qy*qy);
        const float* R = rot + (size_t)row*9;
        #pragma unroll
        for (int i = 0; i < 3; i++)
            #pragma unroll
            for (int kcol = 0; kcol < 3; kcol++)
                out_rot[(size_t)row*9 + i*3 + kcol] =
                    R[i*3+0]*Ru[0*3+kcol] + R[i*3+1]*Ru[1*3+kcol] + R[i*3+2]*Ru[2*3+kcol];
        #pragma unroll
        for (int i = 0; i < 3; i++)
            out_trans[(size_t)row*3 + i] =
                R[i*3+0]*v6[3] + R[i*3+1]*v6[4] + R[i*3+2]*v6[5] + trans[(size_t)row*3 + i];
    }
}

// ---------------- host orchestration (single stream) -------------------------
extern "C" void kernel_launch(void* const* d_in, const int* in_sizes, int n_in,
                              void* d_out, int out_size)
{
    (void)in_sizes; (void)n_in; (void)out_size;
    const float* s       = (const float*)d_in[0];
    const float* rot     = (const float*)d_in[1];
    const float* trans   = (const float*)d_in[2];
    const float* z       = (const float*)d_in[3];
    const float* nzw     = (const float*)d_in[5];
    const float* n1      = (const float*)d_in[6];
    const float* n2      = (const float*)d_in[7];
    const float* n3      = (const float*)d_in[8];
    const float* w_qkv   = (const float*)d_in[9];
    const float* w_qpts  = (const float*)d_in[10];
    const float* w_kpts  = (const float*)d_in[11];
    const float* w_vpts  = (const float*)d_in[12];
    const float* head_w  = (const float*)d_in[13];
    const float* w_pair  = (const float*)d_in[14];
    const float* w_out   = (const float*)d_in[15];
    const float* w12     = (const float*)d_in[16];
    const float* w3      = (const float*)d_in[17];
    const float* w_frame = (const float*)d_in[18];

    float* out       = (float*)d_out;
    float* out_s     = out;
    float* out_rot   = out + (size_t)cBN * cCS;
    float* out_trans = out_rot + (size_t)cBN * 9;

    float *p_s0, *p_wcat, *p_proj, *p_cat, *p_s1, *p_x, *p_hh, *p_x3, *p_part;
    unsigned *p_ahi, *p_alo, *p_whi, *p_wlo;
    cudaGetSymbolAddress((void**)&p_s0,   g_s0);
    cudaGetSymbolAddress((void**)&p_wcat, g_wcat);
    cudaGetSymbolAddress((void**)&p_proj, g_proj);
    cudaGetSymbolAddress((void**)&p_cat,  g_cat);
    cudaGetSymbolAddress((void**)&p_s1,   g_s1);
    cudaGetSymbolAddress((void**)&p_x,    g_x);
    cudaGetSymbolAddress((void**)&p_hh,   g_hh);
    cudaGetSymbolAddress((void**)&p_x3,   g_x3);
    cudaGetSymbolAddress((void**)&p_part, g_part);
    cudaGetSymbolAddress((void**)&p_ahi,  g_ahi);
    cudaGetSymbolAddress((void**)&p_alo,  g_alo);
    cudaGetSymbolAddress((void**)&p_whi,  g_whi);
    cudaGetSymbolAddress((void**)&p_wlo,  g_wlo);

    static int smem_set = 0;
    if (!smem_set) {
        cudaFuncSetAttribute(logits_opair_kernel,
            cudaFuncAttributeMaxDynamicSharedMemorySize, 104448);
        smem_set = 1;
    }

    // 1. s0 = rmsnorm(s); weight concat + splits; activation split
    rmsnorm_kernel<<<cBN, 128>>>(s, n1, p_s0, cCS);
    wcat_kernel<<<648, 256>>>(w_qkv, w_qpts, w_kpts, w_vpts);
    split_t_kernel<<<dim3(16,6), 256>>>(p_s0, p_ahi, p_alo, 384, 1024);
    split_t_kernel<<<dim3(27,6), 256>>>(p_wcat, p_whi+OFF_WCAT, p_wlo+OFF_WCAT, 384, 1728);
    // 2. merged projection GEMM
    gemm_bf16_kernel<<<dim3(27,8,1), 128>>>(p_ahi, p_alo, p_whi+OFF_WCAT, p_wlo+OFF_WCAT,
                                            nullptr, p_proj, 1728, 192);
    // 3. rope + points (merged)
    rope_points_kernel<<<cBN, 384>>>(rot, trans, head_w);
    // 4. pre-bias logits; fused bias+softmax+opair (two pipelined z passes)
    attP_kernel<<<dim3(8,8,24), 256>>>(head_w);
    logits_opair_kernel<<<cBN, 256, 104448>>>(z, nzw, w_pair);
    // 5. o/op outputs + epilogue
    o_op_kernel<<<dim3(8,24), 256>>>();
    op_epilogue_kernel<<<cBN, 96>>>(rot, trans);
    // 6. output projection (split-K=4) + fused combine/rmsnorm
    split_t_kernel<<<dim3(16,36), 256>>>(p_cat, p_ahi, p_alo, 2304, 1024);
    split_t_kernel<<<dim3(6,36), 256>>>(w_out, p_whi+OFF_WOUT, p_wlo+OFF_WOUT, 2304, 384);
    gemm_bf16_kernel<<<dim3(6,8,4), 128>>>(p_ahi, p_alo, p_whi+OFF_WOUT, p_wlo+OFF_WOUT,
                                           nullptr, p_part, 384, 288);
    combine4_rms_kernel<<<cBN, 128>>>(s, n2, p_s1, p_x);
    // 7. transition FFN
    split_t_kernel<<<dim3(16,6), 256>>>(p_x, p_ahi, p_alo, 384, 1024);
    split_t_kernel<<<dim3(48,6), 256>>>(w12, p_whi+OFF_W12, p_wlo+OFF_W12, 384, 3072);
    gemm_bf16_kernel<<<dim3(48,8,1), 128>>>(p_ahi, p_alo, p_whi+OFF_W12, p_wlo+OFF_W12,
                                            nullptr, p_hh, 3072, 192);
    split_gated_t_kernel<<<dim3(16,24), 256>>>(p_ahi, p_alo);
    split_t_kernel<<<dim3(6,24), 256>>>(w3, p_whi+OFF_W3, p_wlo+OFF_W3, 1536, 384);
    gemm_bf16_kernel<<<dim3(6,8,4), 128>>>(p_ahi, p_alo, p_whi+OFF_W3, p_wlo+OFF_W3,
                                           nullptr, p_part, 384, 192);
    combine4_rms_kernel<<<cBN, 128>>>(p_s1, n3, out_s, p_x3);
    // 8. frame update
    frame_kernel<<<cBN, 192>>>(w_frame, rot, trans, out_rot, out_trans);
}